// round 13
// baseline (speedup 1.0000x reference)
#include <cuda_runtime.h>
#include <cstdint>

// ExodusNet: per-timestep dense (32 -> 1), ExpLeak scan, LIF scan with
// SingleSpike + MembraneSubtract.  x: (B, 32, 100) fp32 (t innermost),
// w: (32) fp32, out: (B, 100) fp32 of 0/1 spikes.
//
// FINAL (verified twice: R9 and R12, 70.14us, rel_err 0.0, DRAM ~79%):
// warp-autonomous 2-stage cp.async.bulk pipeline.  Each warp owns 8
// contiguous batch rows, streams them through a private 2-stage SMEM ring
// (12800B per copy), computes weighted currents with float4 SMEM reads +
// a sequential f-chain, runs both scans on 8 lanes, writes spikes out
// coalesced.  No inter-warp coupling after init.
//
// Why this is the ceiling: compulsory traffic is 432MB (x read once, out
// written once); measured 6.28 TB/s equals the full-chip LTS throughput cap
// (~6300 B/cyc, path-independent per B300 microarch data), and kernel-dur
// 68.9us == 432MB / 6.28TB/s.  Five alternative architectures (LDG-based,
// 2/4-block TMA, coarser copies + bulk S2G writeout, deeper ring,
// persistent warps) all matched or regressed.

namespace {

constexpr int T_STEPS    = 100;
constexpr int F_DIM      = 32;
constexpr int ROW_FLOATS = F_DIM * T_STEPS;        // 3200 floats per row
constexpr int CHUNK      = ROW_FLOATS * 4;         // 12800 bytes per row
constexpr int THREADS    = 64;                     // 2 warps
constexpr int NWARP      = THREADS / 32;           // 2
constexpr int B_PER_WARP = 8;
constexpr int BPB        = NWARP * B_PER_WARP;     // 16
constexpr int NSTAGE     = 2;                      // ring depth per warp
constexpr int SM_STRIDE  = 101;                    // conflict-free scan reads

// dynamic smem layout (bytes)
constexpr int WSH_OFF   = 0;                                   // 32 floats
constexpr int MBAR_OFF  = 128;                                 // NWARP*NSTAGE*8
constexpr int ISH_OFF   = 192;                                 // BPB*SM_STRIDE floats
constexpr int ISH_BYTES = BPB * SM_STRIDE * 4;                 // 6464
constexpr int RING_OFF  = ISH_OFF + ((ISH_BYTES + 15) & ~15);  // 16B aligned
constexpr int SMEM_BYTES = RING_OFF + NWARP * NSTAGE * CHUNK;  // ~57.9 KB

__device__ __forceinline__ float alpha_f() { return (float)0.9048374180359595; }
__device__ __forceinline__ float one_m_a() { return (float)(1.0 - 0.9048374180359595); }

__device__ __forceinline__ uint32_t smem_u32(const void* p) {
    uint32_t a;
    asm("{ .reg .u64 t; cvta.to.shared.u64 t, %1; cvt.u32.u64 %0, t; }"
        : "=r"(a) : "l"(p));
    return a;
}
__device__ __forceinline__ void mbar_init(uint32_t mbar, uint32_t cnt) {
    asm volatile("mbarrier.init.shared.b64 [%0], %1;" :: "r"(mbar), "r"(cnt) : "memory");
}
__device__ __forceinline__ void mbar_expect_tx(uint32_t mbar, uint32_t bytes) {
    asm volatile("mbarrier.arrive.expect_tx.shared.b64 _, [%0], %1;"
                 :: "r"(mbar), "r"(bytes) : "memory");
}
__device__ __forceinline__ void bulk_copy_g2s(uint32_t dst_smem, const void* src_gmem,
                                              uint32_t bytes, uint32_t mbar) {
    asm volatile(
        "cp.async.bulk.shared::cluster.global.mbarrier::complete_tx::bytes "
        "[%0], [%1], %2, [%3];"
        :: "r"(dst_smem), "l"(src_gmem), "r"(bytes), "r"(mbar) : "memory");
}
__device__ __forceinline__ void mbar_wait_parity(uint32_t mbar, uint32_t parity) {
    asm volatile(
        "{\n\t"
        ".reg .pred P1;\n\t"
        "WAIT_LOOP_%=:\n\t"
        "mbarrier.try_wait.parity.acquire.cta.shared::cta.b64 P1, [%0], %1, 0x989680;\n\t"
        "@P1 bra.uni WAIT_DONE_%=;\n\t"
        "bra.uni WAIT_LOOP_%=;\n\t"
        "WAIT_DONE_%=:\n\t"
        "}"
        :: "r"(mbar), "r"(parity) : "memory");
}

__global__ __launch_bounds__(THREADS)
void exodus_kernel(const float* __restrict__ x,
                   const float* __restrict__ w,
                   float* __restrict__ out,
                   int B)
{
    extern __shared__ __align__(16) unsigned char smem_raw[];
    float* wsh = reinterpret_cast<float*>(smem_raw + WSH_OFF);
    float* ish = reinterpret_cast<float*>(smem_raw + ISH_OFF);

    const uint32_t smem_base = smem_u32(smem_raw);
    const int tid  = threadIdx.x;
    const int warp = tid >> 5;
    const int lane = tid & 31;
    const int b0   = blockIdx.x * BPB;

    if (tid < F_DIM) wsh[tid] = w[tid];
    if (tid == 0) {
        #pragma unroll
        for (int m = 0; m < NWARP * NSTAGE; ++m)
            mbar_init(smem_base + MBAR_OFF + m * 8, 1);
    }
    __syncthreads();   // only block-wide barrier (init + wsh visibility)

    // ---------------- Phase 1: TMA-streamed weighted currents ------------------
    const int      wb_base   = b0 + warp * B_PER_WARP;          // warp's first b
    const uint32_t ring_base = smem_base + RING_OFF + warp * (NSTAGE * CHUNK);
    const uint32_t mbar_base = smem_base + MBAR_OFF + warp * (NSTAGE * 8);
    float* ish_w = ish + warp * (B_PER_WARP * SM_STRIDE);

    // prologue: fill both stages
    if (lane == 0) {
        #pragma unroll
        for (int s = 0; s < NSTAGE; ++s) {
            const int b = wb_base + s;
            if (b < B) {
                mbar_expect_tx(mbar_base + s * 8, CHUNK);
                bulk_copy_g2s(ring_base + s * CHUNK, x + (size_t)b * ROW_FLOATS,
                              CHUNK, mbar_base + s * 8);
            }
        }
    }

    #pragma unroll
    for (int i = 0; i < B_PER_WARP; ++i) {
        const int b = wb_base + i;
        if (b >= B) break;
        const int s  = i & 1;
        const int ph = (i >> 1) & 1;
        mbar_wait_parity(mbar_base + s * 8, (uint32_t)ph);

        if (lane < 25) {
            const float* stage =
                reinterpret_cast<const float*>(smem_raw + RING_OFF +
                                               warp * (NSTAGE * CHUNK) + s * CHUNK);
            const float* base = stage + 4 * lane;
            float4 acc = make_float4(0.f, 0.f, 0.f, 0.f);
            #pragma unroll
            for (int f = 0; f < F_DIM; ++f) {
                const float4 xa = *reinterpret_cast<const float4*>(base + f * T_STEPS);
                const float wf = wsh[f];
                acc.x = fmaf(xa.x, wf, acc.x);
                acc.y = fmaf(xa.y, wf, acc.y);
                acc.z = fmaf(xa.z, wf, acc.z);
                acc.w = fmaf(xa.w, wf, acc.w);
            }
            float* ip = ish_w + i * SM_STRIDE + 4 * lane;
            ip[0] = acc.x;
            ip[1] = acc.y;
            ip[2] = acc.z;
            ip[3] = acc.w;
        }
        __syncwarp();   // all lanes done reading stage s before reissue

        const int nxt = i + NSTAGE;
        if (nxt < B_PER_WARP && lane == 0) {
            const int nb = wb_base + nxt;
            if (nb < B) {
                mbar_expect_tx(mbar_base + s * 8, CHUNK);
                bulk_copy_g2s(ring_base + s * CHUNK, x + (size_t)nb * ROW_FLOATS,
                              CHUNK, mbar_base + s * 8);
            }
        }
    }
    __syncwarp();

    // ---------------- Phase 2: sequential scans, warp-local (8 lanes) ----------
    // syn[t] = a*syn[t-1] + i[t]
    // v[t]   = a*v[t-1] + (1-a)*syn[t];  s = (v >= 1);  v -= s
    if (lane < B_PER_WARP && (wb_base + lane) < B) {
        float* ip = ish_w + lane * SM_STRIDE;
        float syn = 0.f, v = 0.f;
        #pragma unroll 4
        for (int t = 0; t < T_STEPS; ++t) {
            const float i = ip[t];
            syn = fmaf(alpha_f(), syn, i);
            v   = fmaf(alpha_f(), v, one_m_a() * syn);
            const float s = (v >= 1.0f) ? 1.0f : 0.0f;
            v -= s;
            ip[t] = s;
        }
    }
    __syncwarp();

    // ---------------- Phase 3: coalesced spike write-out (warp-local) ----------
    for (int k = 0; k < B_PER_WARP; ++k) {
        const int b = wb_base + k;
        if (b >= B) break;
        float* op       = out + (size_t)b * T_STEPS;
        const float* ip = ish_w + k * SM_STRIDE;
        #pragma unroll
        for (int j = 0; j < 4; ++j) {
            const int t = lane + 32 * j;
            if (t < T_STEPS) op[t] = ip[t];
        }
    }
}

} // namespace

extern "C" void kernel_launch(void* const* d_in, const int* in_sizes, int n_in,
                              void* d_out, int out_size)
{
    const float* x = (const float*)d_in[0];
    const float* w = (const float*)d_in[1];
    float* out     = (float*)d_out;

    const int B = in_sizes[0] / ROW_FLOATS;   // 32768

    cudaFuncSetAttribute(exodus_kernel,
                         cudaFuncAttributeMaxDynamicSharedMemorySize, SMEM_BYTES);

    const int grid = (B + BPB - 1) / BPB;     // 2048
    exodus_kernel<<<grid, THREADS, SMEM_BYTES>>>(x, w, out, B);
}

// round 14
// speedup vs baseline: 1.0324x; 1.0324x over previous
#include <cuda_runtime.h>
#include <cstdint>

// ExodusNet: per-timestep dense (32 -> 1), ExpLeak scan, LIF scan with
// SingleSpike + MembraneSubtract.  x: (B, 32, 100) fp32 (t innermost),
// w: (32) fp32, out: (B, 100) fp32 of 0/1 spikes.
//
// FINAL (verified three times: R9/R12 70.14us, R13 72.4us -- the spread is
// documented LTS-cap run-to-run variation, not kernel behavior):
// warp-autonomous 2-stage cp.async.bulk pipeline.  Each warp owns 8
// contiguous batch rows, streams them through a private 2-stage SMEM ring
// (12800B per copy), computes weighted currents with float4 SMEM reads +
// a sequential f-chain, runs both scans on 8 lanes, writes spikes out
// coalesced.  No inter-warp coupling after init.
//
// Ceiling argument: compulsory traffic is 432MB (x read once, out written
// once); measured 6.10-6.28 TB/s equals the full-chip LTS throughput cap
// (~6100-6300 B/cyc run-to-run, path-independent); kernel-dur equals
// 432MB / measured-BW on every run.  Five alternative architectures
// (LDG-based, 2/4-block TMA, coarser copies + bulk S2G writeout, deeper
// ring, persistent warps) all matched or regressed.

namespace {

constexpr int T_STEPS    = 100;
constexpr int F_DIM      = 32;
constexpr int ROW_FLOATS = F_DIM * T_STEPS;        // 3200 floats per row
constexpr int CHUNK      = ROW_FLOATS * 4;         // 12800 bytes per row
constexpr int THREADS    = 64;                     // 2 warps
constexpr int NWARP      = THREADS / 32;           // 2
constexpr int B_PER_WARP = 8;
constexpr int BPB        = NWARP * B_PER_WARP;     // 16
constexpr int NSTAGE     = 2;                      // ring depth per warp
constexpr int SM_STRIDE  = 101;                    // conflict-free scan reads

// dynamic smem layout (bytes)
constexpr int WSH_OFF   = 0;                                   // 32 floats
constexpr int MBAR_OFF  = 128;                                 // NWARP*NSTAGE*8
constexpr int ISH_OFF   = 192;                                 // BPB*SM_STRIDE floats
constexpr int ISH_BYTES = BPB * SM_STRIDE * 4;                 // 6464
constexpr int RING_OFF  = ISH_OFF + ((ISH_BYTES + 15) & ~15);  // 16B aligned
constexpr int SMEM_BYTES = RING_OFF + NWARP * NSTAGE * CHUNK;  // ~57.9 KB

__device__ __forceinline__ float alpha_f() { return (float)0.9048374180359595; }
__device__ __forceinline__ float one_m_a() { return (float)(1.0 - 0.9048374180359595); }

__device__ __forceinline__ uint32_t smem_u32(const void* p) {
    uint32_t a;
    asm("{ .reg .u64 t; cvta.to.shared.u64 t, %1; cvt.u32.u64 %0, t; }"
        : "=r"(a) : "l"(p));
    return a;
}
__device__ __forceinline__ void mbar_init(uint32_t mbar, uint32_t cnt) {
    asm volatile("mbarrier.init.shared.b64 [%0], %1;" :: "r"(mbar), "r"(cnt) : "memory");
}
__device__ __forceinline__ void mbar_expect_tx(uint32_t mbar, uint32_t bytes) {
    asm volatile("mbarrier.arrive.expect_tx.shared.b64 _, [%0], %1;"
                 :: "r"(mbar), "r"(bytes) : "memory");
}
__device__ __forceinline__ void bulk_copy_g2s(uint32_t dst_smem, const void* src_gmem,
                                              uint32_t bytes, uint32_t mbar) {
    asm volatile(
        "cp.async.bulk.shared::cluster.global.mbarrier::complete_tx::bytes "
        "[%0], [%1], %2, [%3];"
        :: "r"(dst_smem), "l"(src_gmem), "r"(bytes), "r"(mbar) : "memory");
}
__device__ __forceinline__ void mbar_wait_parity(uint32_t mbar, uint32_t parity) {
    asm volatile(
        "{\n\t"
        ".reg .pred P1;\n\t"
        "WAIT_LOOP_%=:\n\t"
        "mbarrier.try_wait.parity.acquire.cta.shared::cta.b64 P1, [%0], %1, 0x989680;\n\t"
        "@P1 bra.uni WAIT_DONE_%=;\n\t"
        "bra.uni WAIT_LOOP_%=;\n\t"
        "WAIT_DONE_%=:\n\t"
        "}"
        :: "r"(mbar), "r"(parity) : "memory");
}

__global__ __launch_bounds__(THREADS)
void exodus_kernel(const float* __restrict__ x,
                   const float* __restrict__ w,
                   float* __restrict__ out,
                   int B)
{
    extern __shared__ __align__(16) unsigned char smem_raw[];
    float* wsh = reinterpret_cast<float*>(smem_raw + WSH_OFF);
    float* ish = reinterpret_cast<float*>(smem_raw + ISH_OFF);

    const uint32_t smem_base = smem_u32(smem_raw);
    const int tid  = threadIdx.x;
    const int warp = tid >> 5;
    const int lane = tid & 31;
    const int b0   = blockIdx.x * BPB;

    if (tid < F_DIM) wsh[tid] = w[tid];
    if (tid == 0) {
        #pragma unroll
        for (int m = 0; m < NWARP * NSTAGE; ++m)
            mbar_init(smem_base + MBAR_OFF + m * 8, 1);
    }
    __syncthreads();   // only block-wide barrier (init + wsh visibility)

    // ---------------- Phase 1: TMA-streamed weighted currents ------------------
    const int      wb_base   = b0 + warp * B_PER_WARP;          // warp's first b
    const uint32_t ring_base = smem_base + RING_OFF + warp * (NSTAGE * CHUNK);
    const uint32_t mbar_base = smem_base + MBAR_OFF + warp * (NSTAGE * 8);
    float* ish_w = ish + warp * (B_PER_WARP * SM_STRIDE);

    // prologue: fill both stages
    if (lane == 0) {
        #pragma unroll
        for (int s = 0; s < NSTAGE; ++s) {
            const int b = wb_base + s;
            if (b < B) {
                mbar_expect_tx(mbar_base + s * 8, CHUNK);
                bulk_copy_g2s(ring_base + s * CHUNK, x + (size_t)b * ROW_FLOATS,
                              CHUNK, mbar_base + s * 8);
            }
        }
    }

    #pragma unroll
    for (int i = 0; i < B_PER_WARP; ++i) {
        const int b = wb_base + i;
        if (b >= B) break;
        const int s  = i & 1;
        const int ph = (i >> 1) & 1;
        mbar_wait_parity(mbar_base + s * 8, (uint32_t)ph);

        if (lane < 25) {
            const float* stage =
                reinterpret_cast<const float*>(smem_raw + RING_OFF +
                                               warp * (NSTAGE * CHUNK) + s * CHUNK);
            const float* base = stage + 4 * lane;
            float4 acc = make_float4(0.f, 0.f, 0.f, 0.f);
            #pragma unroll
            for (int f = 0; f < F_DIM; ++f) {
                const float4 xa = *reinterpret_cast<const float4*>(base + f * T_STEPS);
                const float wf = wsh[f];
                acc.x = fmaf(xa.x, wf, acc.x);
                acc.y = fmaf(xa.y, wf, acc.y);
                acc.z = fmaf(xa.z, wf, acc.z);
                acc.w = fmaf(xa.w, wf, acc.w);
            }
            float* ip = ish_w + i * SM_STRIDE + 4 * lane;
            ip[0] = acc.x;
            ip[1] = acc.y;
            ip[2] = acc.z;
            ip[3] = acc.w;
        }
        __syncwarp();   // all lanes done reading stage s before reissue

        const int nxt = i + NSTAGE;
        if (nxt < B_PER_WARP && lane == 0) {
            const int nb = wb_base + nxt;
            if (nb < B) {
                mbar_expect_tx(mbar_base + s * 8, CHUNK);
                bulk_copy_g2s(ring_base + s * CHUNK, x + (size_t)nb * ROW_FLOATS,
                              CHUNK, mbar_base + s * 8);
            }
        }
    }
    __syncwarp();

    // ---------------- Phase 2: sequential scans, warp-local (8 lanes) ----------
    // syn[t] = a*syn[t-1] + i[t]
    // v[t]   = a*v[t-1] + (1-a)*syn[t];  s = (v >= 1);  v -= s
    if (lane < B_PER_WARP && (wb_base + lane) < B) {
        float* ip = ish_w + lane * SM_STRIDE;
        float syn = 0.f, v = 0.f;
        #pragma unroll 4
        for (int t = 0; t < T_STEPS; ++t) {
            const float i = ip[t];
            syn = fmaf(alpha_f(), syn, i);
            v   = fmaf(alpha_f(), v, one_m_a() * syn);
            const float s = (v >= 1.0f) ? 1.0f : 0.0f;
            v -= s;
            ip[t] = s;
        }
    }
    __syncwarp();

    // ---------------- Phase 3: coalesced spike write-out (warp-local) ----------
    for (int k = 0; k < B_PER_WARP; ++k) {
        const int b = wb_base + k;
        if (b >= B) break;
        float* op       = out + (size_t)b * T_STEPS;
        const float* ip = ish_w + k * SM_STRIDE;
        #pragma unroll
        for (int j = 0; j < 4; ++j) {
            const int t = lane + 32 * j;
            if (t < T_STEPS) op[t] = ip[t];
        }
    }
}

} // namespace

extern "C" void kernel_launch(void* const* d_in, const int* in_sizes, int n_in,
                              void* d_out, int out_size)
{
    const float* x = (const float*)d_in[0];
    const float* w = (const float*)d_in[1];
    float* out     = (float*)d_out;

    const int B = in_sizes[0] / ROW_FLOATS;   // 32768

    cudaFuncSetAttribute(exodus_kernel,
                         cudaFuncAttributeMaxDynamicSharedMemorySize, SMEM_BYTES);

    const int grid = (B + BPB - 1) / BPB;     // 2048
    exodus_kernel<<<grid, THREADS, SMEM_BYTES>>>(x, w, out, B);
}